// round 6
// baseline (speedup 1.0000x reference)
#include <cuda_runtime.h>
#include <math.h>

#define HI    256
#define WI    256
#define NPIX  262144
#define PPB   128              // pixels per block
#define NTH   256              // 8 warps
#define H1S   68               // h1 row stride (floats), px-major
#define H2TS  130              // h2t row stride (floats), k-major
#define XCS   65

typedef unsigned long long u64;

__device__ float g_xt[HI * WI * 64];   // x transposed to [y][x][c], 16 MB

struct __align__(16) Smem {
    float pose[3][PPB];        //  1536 B
    int   iy[PPB];             //   512 B
    int   ix[PPB];             //   512 B
    float xc[PPB][XCS];        // 33280 B
    union {
        float h1[PPB][H1S];    // 34816 B
        float red[8][PPB][3];  // 12288 B
        u64   dws[8 * 145];    //  9280 B  [px-pair][c*9+tap], f32x2 (even,odd px)
    } u;
    float h2t[256][H2TS];      // 133120 B
};                              // 203776 B total

__device__ __forceinline__ u64 ffma2(u64 a, u64 b, u64 c) {
    u64 d; asm("fma.rn.f32x2 %0,%1,%2,%3;" : "=l"(d) : "l"(a), "l"(b), "l"(c)); return d;
}
__device__ __forceinline__ u64 add2(u64 a, u64 b) {
    u64 d; asm("add.rn.f32x2 %0,%1,%2;" : "=l"(d) : "l"(a), "l"(b)); return d;
}
__device__ __forceinline__ u64 dup2(float f) {
    u64 d; asm("mov.b64 %0,{%1,%1};" : "=l"(d) : "f"(f)); return d;
}
__device__ __forceinline__ u64 pack2(float x, float y) {
    u64 d; asm("mov.b64 %0,{%1,%2};" : "=l"(d) : "f"(x), "f"(y)); return d;
}
__device__ __forceinline__ float2 unpk(u64 a) {
    float2 r; asm("mov.b64 {%0,%1},%2;" : "=f"(r.x), "=f"(r.y) : "l"(a)); return r;
}
__device__ __forceinline__ float hadd2(u64 a) { float2 r = unpk(a); return r.x + r.y; }

// ======== prep: x[64][256][256] -> g_xt[y][x][64] ========
__global__ void __launch_bounds__(256)
transpose_x_kernel(const float* __restrict__ x) {
    extern __shared__ float tile[];   // [64][257]
    const int y   = blockIdx.x;
    const int tid = threadIdx.x;
    for (int i = tid; i < 64 * 256; i += 256) {
        int c = i >> 8, xx = i & 255;
        tile[c * 257 + xx] = __ldg(x + c * 65536 + y * 256 + xx);
    }
    __syncthreads();
    for (int i = tid; i < 64 * 256; i += 256) {
        int xx = i >> 6, c = i & 63;
        g_xt[(y * 256 + xx) * 64 + c] = tile[c * 257 + xx];
    }
}

// ---- layer 1: h1[p][o] = relu(W1[o,:3] @ pose[:,p] + b1[o]) ----
__device__ __forceinline__ void mlp_h1(Smem& s, const float* __restrict__ w1,
                                       const float* __restrict__ b1, int tid) {
    int o  = tid & 63;
    int pb = tid >> 6;              // 4 groups of 32 pixels
    float wa = __ldg(w1 + o * 3 + 0);
    float wb = __ldg(w1 + o * 3 + 1);
    float wc = __ldg(w1 + o * 3 + 2);
    float bb = __ldg(b1 + o);
    #pragma unroll 4
    for (int p = pb * 32; p < pb * 32 + 32; p++) {
        float v = fmaf(wa, s.pose[0][p],
                  fmaf(wb, s.pose[1][p],
                  fmaf(wc, s.pose[2][p], bb)));
        s.u.h1[p][o] = fmaxf(v, 0.f);
    }
}

// ---- layer 2: h2t[o][p] = relu(W2 @ h1 + b2), k-major output ----
// 8 warps: warp -> 32 outputs, lane -> pixels {l, l+32, l+64, l+96}
__device__ __forceinline__ void mlp_h2(Smem& s, const float* __restrict__ w2,
                                       const float* __restrict__ b2,
                                       int warp, int lane) {
    const ulonglong2* ha = reinterpret_cast<const ulonglong2*>(s.u.h1[lane]);
    const ulonglong2* hb = reinterpret_cast<const ulonglong2*>(s.u.h1[lane + 32]);
    const ulonglong2* hc = reinterpret_cast<const ulonglong2*>(s.u.h1[lane + 64]);
    const ulonglong2* hd = reinterpret_cast<const ulonglong2*>(s.u.h1[lane + 96]);
    const int obase = warp * 32;

    #pragma unroll 1
    for (int g = 0; g < 8; g++) {
        const int o = obase + g * 4;
        const ulonglong2* wr = reinterpret_cast<const ulonglong2*>(w2 + o * 64);
        u64 acc[4][4];
        #pragma unroll
        for (int oi = 0; oi < 4; oi++)
            #pragma unroll
            for (int j = 0; j < 4; j++) acc[oi][j] = 0ull;

        #pragma unroll 2
        for (int k4 = 0; k4 < 16; k4++) {
            ulonglong2 va = ha[k4], vb = hb[k4], vc = hc[k4], vd = hd[k4];
            #pragma unroll
            for (int oi = 0; oi < 4; oi++) {
                ulonglong2 wv = wr[oi * 16 + k4];
                acc[oi][0] = ffma2(wv.x, va.x, acc[oi][0]);
                acc[oi][0] = ffma2(wv.y, va.y, acc[oi][0]);
                acc[oi][1] = ffma2(wv.x, vb.x, acc[oi][1]);
                acc[oi][1] = ffma2(wv.y, vb.y, acc[oi][1]);
                acc[oi][2] = ffma2(wv.x, vc.x, acc[oi][2]);
                acc[oi][2] = ffma2(wv.y, vc.y, acc[oi][2]);
                acc[oi][3] = ffma2(wv.x, vd.x, acc[oi][3]);
                acc[oi][3] = ffma2(wv.y, vd.y, acc[oi][3]);
            }
        }
        #pragma unroll
        for (int oi = 0; oi < 4; oi++) {
            float b = __ldg(b2 + o + oi);
            s.h2t[o + oi][lane]      = fmaxf(hadd2(acc[oi][0]) + b, 0.f);
            s.h2t[o + oi][lane + 32] = fmaxf(hadd2(acc[oi][1]) + b, 0.f);
            s.h2t[o + oi][lane + 64] = fmaxf(hadd2(acc[oi][2]) + b, 0.f);
            s.h2t[o + oi][lane + 96] = fmaxf(hadd2(acc[oi][3]) + b, 0.f);
        }
    }
}

// ---- per-(px,c) double-softmax tail ----
__device__ __forceinline__ float pixel_tail2(const float* dwv, const float* h, float sg) {
    float m = dwv[0];
    #pragma unroll
    for (int t = 1; t < 9; t++) m = fmaxf(m, dwv[t]);
    float es = 0.f, hm = 0.f;
    #pragma unroll
    for (int t = 0; t < 9; t++) {
        float e = __expf(dwv[t] - m);
        es += e;
        hm  = fmaf(h[t], e, hm);
    }
    float mean = hm / es;

    float bw[9], m2 = -3.4e38f;
    #pragma unroll
    for (int t = 0; t < 9; t++) {
        float d = h[t] - mean;
        bw[t] = fmaf(sg * d, d, dwv[t]);
        m2 = fmaxf(m2, bw[t]);
    }
    float s2 = 0.f, xcv = 0.f;
    #pragma unroll
    for (int t = 0; t < 9; t++) {
        float ee = __expf(bw[t] - m2);
        s2  += ee;
        xcv  = fmaf(h[t], ee, xcv);
    }
    return xcv / s2;
}

__global__ void __launch_bounds__(NTH, 1)
biupsampler_fused(const float* __restrict__ x,
                  const float* __restrict__ poseMap,
                  const int*   __restrict__ imY,
                  const int*   __restrict__ imX,
                  const float* __restrict__ sigmar,
                  const float* __restrict__ dw_w1, const float* __restrict__ dw_b1,
                  const float* __restrict__ dw_w2, const float* __restrict__ dw_b2,
                  const float* __restrict__ dw_w3, const float* __restrict__ dw_b3,
                  const float* __restrict__ pw_w1, const float* __restrict__ pw_b1,
                  const float* __restrict__ pw_w2, const float* __restrict__ pw_b2,
                  const float* __restrict__ pw_w3, const float* __restrict__ pw_b3,
                  float* __restrict__ out)
{
    extern __shared__ __align__(16) unsigned char smem_raw[];
    Smem& s = *reinterpret_cast<Smem*>(smem_raw);

    const int tid  = threadIdx.x;
    const int warp = tid >> 5;
    const int lane = tid & 31;
    const int pix0 = blockIdx.x * PPB;
    const int col  = 2 * lane;     // pair A: col,col+1 ; pair B: col+64,col+65

    // ---- stage 0 ----
    for (int i = tid; i < 3 * PPB; i += NTH) {
        int j = i >> 7, p = i & 127;
        s.pose[j][p] = __ldg(poseMap + j * NPIX + pix0 + p);
    }
    if (tid < PPB)           s.iy[tid]       = __ldg(imY + pix0 + tid);
    else if (tid < 2 * PPB)  s.ix[tid - PPB] = __ldg(imX + pix0 + tid - PPB);
    __syncthreads();

    // ===================== DW branch =====================
    mlp_h1(s, dw_w1, dw_b1, tid);
    __syncthreads();
    mlp_h2(s, dw_w2, dw_b2, warp, lane);
    __syncthreads();

    // ---- pass 1: 2-channel-blocked GEMM -> stage dw -> coalesced gather tail ----
    #pragma unroll 1
    for (int c4 = 0; c4 < 4; c4++) {
        const int c0 = c4 * 16 + warp * 2;          // channels c0, c0+1
        const float4* wr0 = reinterpret_cast<const float4*>(dw_w3 + c0 * 9 * 256);
        const float4* wr1 = reinterpret_cast<const float4*>(dw_w3 + (c0 + 1) * 9 * 256);

        u64 acc[2][9][2];
        #pragma unroll
        for (int cb = 0; cb < 2; cb++)
            #pragma unroll
            for (int t = 0; t < 9; t++) { acc[cb][t][0] = 0ull; acc[cb][t][1] = 0ull; }

        #pragma unroll 1
        for (int k4 = 0; k4 < 64; k4++) {
            const int k = k4 * 4;
            u64 hA0 = *(const u64*)&s.h2t[k + 0][col];
            u64 hA1 = *(const u64*)&s.h2t[k + 1][col];
            u64 hA2 = *(const u64*)&s.h2t[k + 2][col];
            u64 hA3 = *(const u64*)&s.h2t[k + 3][col];
            u64 hB0 = *(const u64*)&s.h2t[k + 0][col + 64];
            u64 hB1 = *(const u64*)&s.h2t[k + 1][col + 64];
            u64 hB2 = *(const u64*)&s.h2t[k + 2][col + 64];
            u64 hB3 = *(const u64*)&s.h2t[k + 3][col + 64];
            #pragma unroll
            for (int t = 0; t < 9; t++) {
                float4 wA = __ldg(wr0 + t * 64 + k4);
                float4 wB = __ldg(wr1 + t * 64 + k4);
                u64 a0 = dup2(wA.x), a1 = dup2(wA.y), a2 = dup2(wA.z), a3 = dup2(wA.w);
                acc[0][t][0] = ffma2(a0, hA0, acc[0][t][0]);
                acc[0][t][0] = ffma2(a1, hA1, acc[0][t][0]);
                acc[0][t][0] = ffma2(a2, hA2, acc[0][t][0]);
                acc[0][t][0] = ffma2(a3, hA3, acc[0][t][0]);
                acc[0][t][1] = ffma2(a0, hB0, acc[0][t][1]);
                acc[0][t][1] = ffma2(a1, hB1, acc[0][t][1]);
                acc[0][t][1] = ffma2(a2, hB2, acc[0][t][1]);
                acc[0][t][1] = ffma2(a3, hB3, acc[0][t][1]);
                u64 b0 = dup2(wB.x), b1 = dup2(wB.y), b2 = dup2(wB.z), b3 = dup2(wB.w);
                acc[1][t][0] = ffma2(b0, hA0, acc[1][t][0]);
                acc[1][t][0] = ffma2(b1, hA1, acc[1][t][0]);
                acc[1][t][0] = ffma2(b2, hA2, acc[1][t][0]);
                acc[1][t][0] = ffma2(b3, hA3, acc[1][t][0]);
                acc[1][t][1] = ffma2(b0, hB0, acc[1][t][1]);
                acc[1][t][1] = ffma2(b1, hB1, acc[1][t][1]);
                acc[1][t][1] = ffma2(b2, hB2, acc[1][t][1]);
                acc[1][t][1] = ffma2(b3, hB3, acc[1][t][1]);
            }
        }

        // add bias, keep f32x2-packed over pixel pairs
        #pragma unroll
        for (int cb = 0; cb < 2; cb++)
            #pragma unroll
            for (int t = 0; t < 9; t++) {
                u64 bv = dup2(__ldg(dw_b3 + (c0 + cb) * 9 + t));
                acc[cb][t][0] = add2(acc[cb][t][0], bv);
                acc[cb][t][1] = add2(acc[cb][t][1], bv);
            }

        // 8 pixel-chunks of 16: stage dw, then 1 thread = 1 (px, c) tail task
        #pragma unroll 1
        for (int j = 0; j < 8; j++) {
            __syncthreads();   // previous chunk's readers done before overwrite
            const int lo = 8 * (j & 3);
            if (lane >= lo && lane < lo + 8) {
                const int sel = j >> 2;             // 0 -> pair A, 1 -> pair B
                u64* dst = &s.u.dws[(lane - lo) * 145];
                #pragma unroll
                for (int cb = 0; cb < 2; cb++)
                    #pragma unroll
                    for (int t = 0; t < 9; t++)
                        dst[(warp * 2 + cb) * 9 + t] = acc[cb][t][sel];
            }
            __syncthreads();

            // tail task: px = 16j + tid/16, c_t = 16*c4 + (tid%16)
            const int pxl  = tid >> 4;              // 0..15
            const int px   = j * 16 + pxl;
            const int cw   = tid & 15;
            const int c_t  = c4 * 16 + cw;
            const int pair = pxl >> 1, par = pxl & 1;

            const float* df = reinterpret_cast<const float*>(&s.u.dws[pair * 145 + cw * 9]);
            float dwv[9];
            #pragma unroll
            for (int t = 0; t < 9; t++) dwv[t] = df[2 * t + par];

            const int iy = s.iy[px], ix = s.ix[px];
            const float sg = __ldg(sigmar + c_t);

            float h[9];
            #pragma unroll
            for (int t = 0; t < 9; t++) {
                int yy = iy + t / 3 - 1;
                int xx = ix + t % 3 - 1;
                bool ok = ((unsigned)yy < HI) && ((unsigned)xx < WI);
                h[t] = ok ? __ldg(&g_xt[(yy * WI + xx) * 64 + c_t]) : 0.f;
            }

            s.xc[px][c_t] = pixel_tail2(dwv, h, sg);
        }
    }
    __syncthreads();

    // ===================== PW branch =====================
    mlp_h1(s, pw_w1, pw_b1, tid);
    __syncthreads();
    mlp_h2(s, pw_w2, pw_b2, warp, lane);
    __syncthreads();

    // ---- pass 2: 2-channel-blocked pw GEMM, contract with xc ----
    {
        u64 oA[3] = {0ull, 0ull, 0ull};
        u64 oB[3] = {0ull, 0ull, 0ull};

        #pragma unroll 1
        for (int c4 = 0; c4 < 4; c4++) {
            const int c0 = warp * 8 + c4 * 2;       // channels c0, c0+1
            const float4* wr0 = reinterpret_cast<const float4*>(pw_w3 + c0 * 3 * 256);
            const float4* wr1 = reinterpret_cast<const float4*>(pw_w3 + (c0 + 1) * 3 * 256);

            u64 acc[2][3][2];
            #pragma unroll
            for (int cb = 0; cb < 2; cb++)
                #pragma unroll
                for (int r = 0; r < 3; r++) { acc[cb][r][0] = 0ull; acc[cb][r][1] = 0ull; }

            #pragma unroll 1
            for (int k4 = 0; k4 < 64; k4++) {
                const int k = k4 * 4;
                u64 hA0 = *(const u64*)&s.h2t[k + 0][col];
                u64 hA1 = *(const u64*)&s.h2t[k + 1][col];
                u64 hA2 = *(const u64*)&s.h2t[k + 2][col];
                u64 hA3 = *(const u64*)&s.h2t[k + 3][col];
                u64 hB0 = *(const u64*)&s.h2t[k + 0][col + 64];
                u64 hB1 = *(const u64*)&s.h2t[k + 1][col + 64];
                u64 hB2 = *(const u64*)&s.h2t[k + 2][col + 64];
                u64 hB3 = *(const u64*)&s.h2t[k + 3][col + 64];
                #pragma unroll
                for (int r = 0; r < 3; r++) {
                    float4 wA = __ldg(wr0 + r * 64 + k4);
                    float4 wB = __ldg(wr1 + r * 64 + k4);
                    u64 a0 = dup2(wA.x), a1 = dup2(wA.y), a2 = dup2(wA.z), a3 = dup2(wA.w);
                    acc[0][r][0] = ffma2(a0, hA0, acc[0][r][0]);
                    acc[0][r][0] = ffma2(a1, hA1, acc[0][r][0]);
                    acc[0][r][0] = ffma2(a2, hA2, acc[0][r][0]);
                    acc[0][r][0] = ffma2(a3, hA3, acc[0][r][0]);
                    acc[0][r][1] = ffma2(a0, hB0, acc[0][r][1]);
                    acc[0][r][1] = ffma2(a1, hB1, acc[0][r][1]);
                    acc[0][r][1] = ffma2(a2, hB2, acc[0][r][1]);
                    acc[0][r][1] = ffma2(a3, hB3, acc[0][r][1]);
                    u64 b0 = dup2(wB.x), b1 = dup2(wB.y), b2 = dup2(wB.z), b3 = dup2(wB.w);
                    acc[1][r][0] = ffma2(b0, hA0, acc[1][r][0]);
                    acc[1][r][0] = ffma2(b1, hA1, acc[1][r][0]);
                    acc[1][r][0] = ffma2(b2, hA2, acc[1][r][0]);
                    acc[1][r][0] = ffma2(b3, hA3, acc[1][r][0]);
                    acc[1][r][1] = ffma2(b0, hB0, acc[1][r][1]);
                    acc[1][r][1] = ffma2(b1, hB1, acc[1][r][1]);
                    acc[1][r][1] = ffma2(b2, hB2, acc[1][r][1]);
                    acc[1][r][1] = ffma2(b3, hB3, acc[1][r][1]);
                }
            }

            #pragma unroll
            for (int cb = 0; cb < 2; cb++) {
                const int c = c0 + cb;
                u64 xA = pack2(s.xc[col][c],      s.xc[col + 1][c]);
                u64 xB = pack2(s.xc[col + 64][c], s.xc[col + 65][c]);
                #pragma unroll
                for (int r = 0; r < 3; r++) {
                    u64 b2v = dup2(__ldg(pw_b3 + c * 3 + r));
                    oA[r] = ffma2(xA, add2(acc[cb][r][0], b2v), oA[r]);
                    oB[r] = ffma2(xB, add2(acc[cb][r][1], b2v), oB[r]);
                }
            }
        }

        #pragma unroll
        for (int r = 0; r < 3; r++) {
            float2 a = unpk(oA[r]);
            float2 b = unpk(oB[r]);
            s.u.red[warp][col][r]      = a.x;
            s.u.red[warp][col + 1][r]  = a.y;
            s.u.red[warp][col + 64][r] = b.x;
            s.u.red[warp][col + 65][r] = b.y;
        }
    }
    __syncthreads();

    // ---- cross-warp channel reduction + output ----
    for (int i = tid; i < 3 * PPB; i += NTH) {
        const int p = i / 3;
        const int r = i - 3 * p;
        float v = 0.f;
        #pragma unroll
        for (int w = 0; w < 8; w++) v += s.u.red[w][p][r];
        out[r * NPIX + pix0 + p] = v;
    }
}

extern "C" void kernel_launch(void* const* d_in, const int* in_sizes, int n_in,
                              void* d_out, int out_size) {
    (void)in_sizes; (void)n_in; (void)out_size;
    const float* x      = (const float*)d_in[0];
    const float* pose   = (const float*)d_in[1];
    const int*   imY    = (const int*)  d_in[2];
    const int*   imX    = (const int*)  d_in[3];
    const float* sigmar = (const float*)d_in[4];
    const float* dw_w1  = (const float*)d_in[5];
    const float* dw_b1  = (const float*)d_in[6];
    const float* dw_w2  = (const float*)d_in[7];
    const float* dw_b2  = (const float*)d_in[8];
    const float* dw_w3  = (const float*)d_in[9];
    const float* dw_b3  = (const float*)d_in[10];
    const float* pw_w1  = (const float*)d_in[11];
    const float* pw_b1  = (const float*)d_in[12];
    const float* pw_w2  = (const float*)d_in[13];
    const float* pw_b2  = (const float*)d_in[14];
    const float* pw_w3  = (const float*)d_in[15];
    const float* pw_b3  = (const float*)d_in[16];
    float* out = (float*)d_out;

    const int tsmem = 64 * 257 * 4;
    cudaFuncSetAttribute(transpose_x_kernel,
                         cudaFuncAttributeMaxDynamicSharedMemorySize, tsmem);
    transpose_x_kernel<<<256, 256, tsmem>>>(x);

    const int smem = (int)sizeof(Smem);
    cudaFuncSetAttribute(biupsampler_fused,
                         cudaFuncAttributeMaxDynamicSharedMemorySize, smem);
    biupsampler_fused<<<NPIX / PPB, NTH, smem>>>(
        x, pose, imY, imX, sigmar,
        dw_w1, dw_b1, dw_w2, dw_b2, dw_w3, dw_b3,
        pw_w1, pw_b1, pw_w2, pw_b2, pw_w3, pw_b3,
        out);
}

// round 7
// speedup vs baseline: 2.6787x; 2.6787x over previous
#include <cuda_runtime.h>
#include <math.h>

#define HI    256
#define WI    256
#define NPIX  262144
#define PPB   128
#define NTH   256

#define H2S   260     // h2 px-major stride (floats): 260%32=4 -> conflict-free frags
#define H1S   68      // h1 px-major stride
#define WTS   132     // weight-tile stride (128 k + pad)
#define SDS   68      // sD staging stride

typedef unsigned int u32;

__device__ float g_xt[HI * WI * 64];          // x transposed [y][x][c]      16 MB
__device__ float g_dw[NPIX * 9 * 64];         // dw scratch  [pix][t][c]    604 MB
__device__ float g_pw[NPIX * 3 * 64];         // pw scratch  [pix][r][c]    201 MB

struct __align__(16) SmemA {
    float h2[PPB * H2S];                       // 133120 B
    float wt[64 * WTS];                        //  33792 B
    union { float h1[PPB * H1S]; float sD[PPB * SDS]; } u;  // 34816 B
    float pose[3][PPB];                        //   1536 B
    float sbias[64];
    float sbias2[64];
};                                             // 203776 B

__device__ __forceinline__ u32 tf32bits(float x) {
    u32 r; asm("cvt.rna.tf32.f32 %0, %1;" : "=r"(r) : "f"(x)); return r;
}
__device__ __forceinline__ float tf32f(float x) { return __uint_as_float(tf32bits(x)); }

__device__ __forceinline__ void mma_tf32(float d[4], const u32 a[4], const u32 b[2]) {
    asm volatile(
        "mma.sync.aligned.m16n8k8.row.col.f32.tf32.tf32.f32 "
        "{%0,%1,%2,%3}, {%4,%5,%6,%7}, {%8,%9}, {%0,%1,%2,%3};"
        : "+f"(d[0]), "+f"(d[1]), "+f"(d[2]), "+f"(d[3])
        : "r"(a[0]), "r"(a[1]), "r"(a[2]), "r"(a[3]), "r"(b[0]), "r"(b[1]));
}

// ======== prep: x[64][256][256] -> g_xt[y][x][64] ========
__global__ void __launch_bounds__(256)
transpose_x_kernel(const float* __restrict__ x) {
    extern __shared__ float tile[];   // [64][257]
    const int y   = blockIdx.x;
    const int tid = threadIdx.x;
    for (int i = tid; i < 64 * 256; i += 256) {
        int c = i >> 8, xx = i & 255;
        tile[c * 257 + xx] = __ldg(x + c * 65536 + y * 256 + xx);
    }
    __syncthreads();
    for (int i = tid; i < 64 * 256; i += 256) {
        int xx = i >> 6, c = i & 63;
        g_xt[(y * 256 + xx) * 64 + c] = tile[c * 257 + xx];
    }
}

// ======== warp GEMM: 32px x 32n tile, m16n8k8 tf32 ========
// A: activations px-major (stride AS); W: weight tile n-major (stride WTS)
template<int KSTEPS, int AS>
__device__ __forceinline__ void warp_gemm(const float* __restrict__ A,
                                          const float* __restrict__ W,
                                          float d[2][4][4],
                                          int px0, int n0, int lane, int acol0)
{
    const float* a0 = A + (px0 + (lane >> 2)) * AS + acol0 + (lane & 3);
    const float* b0 = W + (n0 + (lane >> 2)) * WTS + (lane & 3);
    #pragma unroll
    for (int ks = 0; ks < KSTEPS; ks++) {
        u32 a[2][4], b[4][2];
        #pragma unroll
        for (int mi = 0; mi < 2; mi++) {
            const float* ap = a0 + mi * 16 * AS + ks * 8;
            a[mi][0] = __float_as_uint(ap[0]);
            a[mi][1] = __float_as_uint(ap[8 * AS]);
            a[mi][2] = __float_as_uint(ap[4]);
            a[mi][3] = __float_as_uint(ap[8 * AS + 4]);
        }
        #pragma unroll
        for (int ni = 0; ni < 4; ni++) {
            const float* bp = b0 + ni * 8 * WTS + ks * 8;
            b[ni][0] = __float_as_uint(bp[0]);
            b[ni][1] = __float_as_uint(bp[4]);
        }
        #pragma unroll
        for (int mi = 0; mi < 2; mi++)
            #pragma unroll
            for (int ni = 0; ni < 4; ni++)
                mma_tf32(d[mi][ni], a[mi], b[ni]);
    }
}

// ======== one MLP branch: h1 -> h2 (mma) -> W3 phases (mma) -> scratch ========
__device__ void run_branch(SmemA& s,
                           const float* __restrict__ w1, const float* __restrict__ b1,
                           const float* __restrict__ w2, const float* __restrict__ b2,
                           const float* __restrict__ w3, const float* __restrict__ b3,
                           float* __restrict__ scratch, int TP, int pix0, int tid)
{
    const int warp = tid >> 5, lane = tid & 31;
    const int px0 = (warp & 3) * 32;
    const int n0  = (warp >> 2) * 32;

    // ---- layer 1 (scalar, tiny): h1[px][o] px-major, tf32-rounded ----
    {
        int o = tid & 63, pb = tid >> 6;
        float wa = __ldg(w1 + o * 3 + 0);
        float wb = __ldg(w1 + o * 3 + 1);
        float wc = __ldg(w1 + o * 3 + 2);
        float bb = __ldg(b1 + o);
        #pragma unroll 4
        for (int p = pb * 32; p < pb * 32 + 32; p++) {
            float v = fmaf(wa, s.pose[0][p],
                      fmaf(wb, s.pose[1][p],
                      fmaf(wc, s.pose[2][p], bb)));
            s.u.h1[p * H1S + o] = tf32f(fmaxf(v, 0.f));
        }
    }
    __syncthreads();

    // ---- layer 2: h2[px][o] = relu(W2 @ h1 + b2), 4 o-chunks of 64, K=64 ----
    for (int och = 0; och < 4; och++) {
        #pragma unroll
        for (int it = 0; it < 4; it++) {
            int idx = tid + it * 256;            // 1024 float4
            int row = idx >> 4, c4 = idx & 15;
            float4 v = __ldg((const float4*)(w2 + (och * 64 + row) * 64) + c4);
            v.x = tf32f(v.x); v.y = tf32f(v.y); v.z = tf32f(v.z); v.w = tf32f(v.w);
            *(float4*)&s.wt[row * WTS + c4 * 4] = v;
        }
        if (tid < 64) s.sbias2[tid] = __ldg(b2 + och * 64 + tid);
        __syncthreads();

        float d[2][4][4];
        #pragma unroll
        for (int mi = 0; mi < 2; mi++)
            #pragma unroll
            for (int ni = 0; ni < 4; ni++)
                #pragma unroll
                for (int j = 0; j < 4; j++) d[mi][ni][j] = 0.f;

        warp_gemm<8, H1S>(s.u.h1, s.wt, d, px0, n0, lane, 0);

        #pragma unroll
        for (int mi = 0; mi < 2; mi++)
            #pragma unroll
            for (int ni = 0; ni < 4; ni++)
                #pragma unroll
                for (int j = 0; j < 4; j++) {
                    int px = px0 + mi * 16 + (lane >> 2) + ((j >> 1) << 3);
                    int ol = n0 + ni * 8 + 2 * (lane & 3) + (j & 1);
                    float v = fmaxf(d[mi][ni][j] + s.sbias2[ol], 0.f);
                    s.h2[px * H2S + och * 64 + ol] = tf32f(v);
                }
        __syncthreads();
    }

    // ---- layer 3: TP phases (tap p, 64 channels), K=256 in 2 chunks of 128 ----
    for (int p = 0; p < TP; p++) {
        float d[2][4][4];
        #pragma unroll
        for (int mi = 0; mi < 2; mi++)
            #pragma unroll
            for (int ni = 0; ni < 4; ni++)
                #pragma unroll
                for (int j = 0; j < 4; j++) d[mi][ni][j] = 0.f;

        for (int kc = 0; kc < 2; kc++) {
            #pragma unroll
            for (int it = 0; it < 8; it++) {
                int idx = tid + it * 256;        // 2048 float4
                int row = idx >> 5, c4 = idx & 31;
                float4 v = __ldg((const float4*)(w3 + (row * TP + p) * 256 + kc * 128) + c4);
                v.x = tf32f(v.x); v.y = tf32f(v.y); v.z = tf32f(v.z); v.w = tf32f(v.w);
                *(float4*)&s.wt[row * WTS + c4 * 4] = v;
            }
            __syncthreads();
            warp_gemm<16, H2S>(s.h2, s.wt, d, px0, n0, lane, kc * 128);
            __syncthreads();
        }

        // stage D to sD[px][c]
        #pragma unroll
        for (int mi = 0; mi < 2; mi++)
            #pragma unroll
            for (int ni = 0; ni < 4; ni++)
                #pragma unroll
                for (int j = 0; j < 4; j++) {
                    int px = px0 + mi * 16 + (lane >> 2) + ((j >> 1) << 3);
                    int c  = n0 + ni * 8 + 2 * (lane & 3) + (j & 1);
                    s.u.sD[px * SDS + c] = d[mi][ni][j];
                }
        if (tid < 64) s.sbias[tid] = __ldg(b3 + tid * TP + p);
        __syncthreads();

        // flush + bias -> scratch[(pix)*TP + p][c], coalesced
        #pragma unroll
        for (int it = 0; it < 8; it++) {
            int idx = tid + it * 256;            // 2048 float4
            int px = idx >> 4, c4 = idx & 15;
            float4 v  = *(const float4*)&s.u.sD[px * SDS + c4 * 4];
            float4 bb = *(const float4*)&s.sbias[c4 * 4];
            v.x += bb.x; v.y += bb.y; v.z += bb.z; v.w += bb.w;
            *((float4*)(scratch + ((pix0 + px) * TP + p) * 64) + c4) = v;
        }
        __syncthreads();
    }
}

__global__ void __launch_bounds__(NTH, 1)
biup_gemm(const float* __restrict__ poseMap,
          const float* __restrict__ dw_w1, const float* __restrict__ dw_b1,
          const float* __restrict__ dw_w2, const float* __restrict__ dw_b2,
          const float* __restrict__ dw_w3, const float* __restrict__ dw_b3,
          const float* __restrict__ pw_w1, const float* __restrict__ pw_b1,
          const float* __restrict__ pw_w2, const float* __restrict__ pw_b2,
          const float* __restrict__ pw_w3, const float* __restrict__ pw_b3)
{
    extern __shared__ __align__(16) unsigned char smem_raw[];
    SmemA& s = *reinterpret_cast<SmemA*>(smem_raw);
    const int tid  = threadIdx.x;
    const int pix0 = blockIdx.x * PPB;

    for (int i = tid; i < 3 * PPB; i += NTH) {
        int j = i >> 7, pp = i & 127;
        s.pose[j][pp] = __ldg(poseMap + j * NPIX + pix0 + pp);
    }
    __syncthreads();

    run_branch(s, dw_w1, dw_b1, dw_w2, dw_b2, dw_w3, dw_b3, g_dw, 9, pix0, tid);
    __syncthreads();
    run_branch(s, pw_w1, pw_b1, pw_w2, pw_b2, pw_w3, pw_b3, g_pw, 3, pix0, tid);
}

// ======== tail kernel: thread = (px, c); lanes = 32 consecutive c ========
__global__ void __launch_bounds__(256)
biup_tail(const int* __restrict__ imY, const int* __restrict__ imX,
          const float* __restrict__ sigmar, float* __restrict__ out)
{
    __shared__ float red[8][3];
    const int tid = threadIdx.x;
    const int c   = tid & 63;
    const int pxl = tid >> 6;
    const int pix = blockIdx.x * 4 + pxl;

    const int iy = __ldg(imY + pix), ix = __ldg(imX + pix);
    const float sg = __ldg(sigmar + c);

    float dwv[9], h[9];
    #pragma unroll
    for (int t = 0; t < 9; t++)
        dwv[t] = __ldg(g_dw + (pix * 9 + t) * 64 + c);
    #pragma unroll
    for (int t = 0; t < 9; t++) {
        int yy = iy + t / 3 - 1;
        int xx = ix + t % 3 - 1;
        bool ok = ((unsigned)yy < HI) && ((unsigned)xx < WI);
        h[t] = ok ? __ldg(&g_xt[(yy * WI + xx) * 64 + c]) : 0.f;
    }

    // softmax(dw) -> mean
    float m = dwv[0];
    #pragma unroll
    for (int t = 1; t < 9; t++) m = fmaxf(m, dwv[t]);
    float es = 0.f, hm = 0.f;
    #pragma unroll
    for (int t = 0; t < 9; t++) {
        float e = __expf(dwv[t] - m);
        es += e;
        hm  = fmaf(h[t], e, hm);
    }
    float mean = hm / es;

    // bw = dw + sg*(h-mean)^2 ; softmax(bw)-weighted sum
    float bw[9], m2 = -3.4e38f;
    #pragma unroll
    for (int t = 0; t < 9; t++) {
        float dd = h[t] - mean;
        bw[t] = fmaf(sg * dd, dd, dwv[t]);
        m2 = fmaxf(m2, bw[t]);
    }
    float s2 = 0.f, xcv = 0.f;
    #pragma unroll
    for (int t = 0; t < 9; t++) {
        float ee = __expf(bw[t] - m2);
        s2  += ee;
        xcv  = fmaf(h[t], ee, xcv);
    }
    float xc = xcv / s2;

    float o0 = xc * __ldg(g_pw + (pix * 3 + 0) * 64 + c);
    float o1 = xc * __ldg(g_pw + (pix * 3 + 1) * 64 + c);
    float o2 = xc * __ldg(g_pw + (pix * 3 + 2) * 64 + c);

    #pragma unroll
    for (int off = 16; off; off >>= 1) {
        o0 += __shfl_xor_sync(0xffffffffu, o0, off);
        o1 += __shfl_xor_sync(0xffffffffu, o1, off);
        o2 += __shfl_xor_sync(0xffffffffu, o2, off);
    }
    if ((tid & 31) == 0) {
        int w = tid >> 5;
        red[w][0] = o0; red[w][1] = o1; red[w][2] = o2;
    }
    __syncthreads();
    if (tid < 12) {
        int pl = tid >> 2;        // 0..2? no: need pl 0..3, r 0..2
        int r  = tid - pl * 4;    // placeholder, fixed below
        // remap cleanly: tid = pl*3 + r
        pl = tid / 3; r = tid - pl * 3;
        out[r * NPIX + blockIdx.x * 4 + pl] = red[2 * pl][r] + red[2 * pl + 1][r];
    }
}

extern "C" void kernel_launch(void* const* d_in, const int* in_sizes, int n_in,
                              void* d_out, int out_size) {
    (void)in_sizes; (void)n_in; (void)out_size;
    const float* x      = (const float*)d_in[0];
    const float* pose   = (const float*)d_in[1];
    const int*   imY    = (const int*)  d_in[2];
    const int*   imX    = (const int*)  d_in[3];
    const float* sigmar = (const float*)d_in[4];
    const float* dw_w1  = (const float*)d_in[5];
    const float* dw_b1  = (const float*)d_in[6];
    const float* dw_w2  = (const float*)d_in[7];
    const float* dw_b2  = (const float*)d_in[8];
    const float* dw_w3  = (const float*)d_in[9];
    const float* dw_b3  = (const float*)d_in[10];
    const float* pw_w1  = (const float*)d_in[11];
    const float* pw_b1  = (const float*)d_in[12];
    const float* pw_w2  = (const float*)d_in[13];
    const float* pw_b2  = (const float*)d_in[14];
    const float* pw_w3  = (const float*)d_in[15];
    const float* pw_b3  = (const float*)d_in[16];
    float* out = (float*)d_out;

    const int tsmem = 64 * 257 * 4;
    cudaFuncSetAttribute(transpose_x_kernel,
                         cudaFuncAttributeMaxDynamicSharedMemorySize, tsmem);
    transpose_x_kernel<<<256, 256, tsmem>>>(x);

    const int asmem = (int)sizeof(SmemA);
    cudaFuncSetAttribute(biup_gemm,
                         cudaFuncAttributeMaxDynamicSharedMemorySize, asmem);
    biup_gemm<<<NPIX / PPB, NTH, asmem>>>(
        pose,
        dw_w1, dw_b1, dw_w2, dw_b2, dw_w3, dw_b3,
        pw_w1, pw_b1, pw_w2, pw_b2, pw_w3, pw_b3);

    biup_tail<<<NPIX / 4, 256>>>(imY, imX, sigmar, out);
}